// round 1
// baseline (speedup 1.0000x reference)
#include <cuda_runtime.h>
#include <cstdint>

#define N_NODES 100000
#define N_EDGES 1600000
#define F 64

// ---------------- static device scratch (no allocations allowed) ----------------
__device__ int   g_deg[N_NODES];
__device__ int   g_off[N_NODES + 1];
__device__ int   g_cursor[N_NODES];
__device__ int   g_bsum[128];
__device__ int   g_csr_src[N_EDGES];
__device__ float g_csr_e[N_EDGES];
__device__ float g_deginv[N_NODES];
__device__ float g_hN[(size_t)N_NODES * F];   // aggregated neighborhood features
__device__ float g_h1[(size_t)N_NODES * F];   // layer-1 output

// ---------------- CSR build ----------------
__global__ void k_zero_deg() {
    int i = blockIdx.x * blockDim.x + threadIdx.x;
    if (i < N_NODES) g_deg[i] = 0;
}

__global__ void k_deg(const int* __restrict__ dst) {
    int i = blockIdx.x * blockDim.x + threadIdx.x;
    if (i < N_EDGES) atomicAdd(&g_deg[dst[i]], 1);
}

__global__ void k_scan_local() {
    __shared__ int sh[1024];
    int i = blockIdx.x * 1024 + threadIdx.x;
    int v = (i < N_NODES) ? g_deg[i] : 0;
    sh[threadIdx.x] = v;
    __syncthreads();
#pragma unroll
    for (int off = 1; off < 1024; off <<= 1) {
        int t = 0;
        if ((int)threadIdx.x >= off) t = sh[threadIdx.x - off];
        __syncthreads();
        sh[threadIdx.x] += t;
        __syncthreads();
    }
    if (i < N_NODES) g_off[i + 1] = sh[threadIdx.x];
    if (threadIdx.x == 1023) g_bsum[blockIdx.x] = sh[1023];
}

__global__ void k_scan_bsum(int nb) {
    __shared__ int sh[128];
    int t = threadIdx.x;
    int v = (t < nb) ? g_bsum[t] : 0;
    sh[t] = v;
    __syncthreads();
#pragma unroll
    for (int off = 1; off < 128; off <<= 1) {
        int x = 0;
        if (t >= off) x = sh[t - off];
        __syncthreads();
        sh[t] += x;
        __syncthreads();
    }
    if (t < nb) g_bsum[t] = sh[t];
}

__global__ void k_scan_add() {
    int i = blockIdx.x * blockDim.x + threadIdx.x;
    if (i < N_NODES) {
        int b = i >> 10;
        if (b > 0) g_off[i + 1] += g_bsum[b - 1];
    }
    if (i == 0) g_off[0] = 0;
}

__global__ void k_cursor_init() {
    int i = blockIdx.x * blockDim.x + threadIdx.x;
    if (i < N_NODES) {
        g_cursor[i] = g_off[i];
        int d = g_deg[i];
        g_deginv[i] = 1.0f / (float)(d > 0 ? d : 1);
    }
}

__global__ void k_fill_csr(const int* __restrict__ src, const int* __restrict__ dst,
                           const float* __restrict__ e) {
    int i = blockIdx.x * blockDim.x + threadIdx.x;
    if (i < N_EDGES) {
        int d = dst[i];
        int pos = atomicAdd(&g_cursor[d], 1);
        g_csr_src[pos] = src[i];
        g_csr_e[pos]   = e[i];
    }
}

// ---------------- aggregation: mean over incoming edges, one warp per node ----------------
// use_h1 == 0: input features come from hext (in_feat); == 1: from g_h1.
__global__ void k_agg(const float* __restrict__ hext, int use_h1) {
    int warp = (blockIdx.x * blockDim.x + threadIdx.x) >> 5;
    int lane = threadIdx.x & 31;
    if (warp >= N_NODES) return;
    const float* __restrict__ h = use_h1 ? (const float*)g_h1 : hext;

    int beg = g_off[warp];
    int end = g_off[warp + 1];
    float acc0 = 0.f, acc1 = 0.f;
#pragma unroll 4
    for (int p = beg; p < end; ++p) {
        int s    = g_csr_src[p];
        float ev = g_csr_e[p];
        const float* row = h + (size_t)s * F;
        acc0 = fmaf(row[lane],      ev, acc0);
        acc1 = fmaf(row[lane + 32], ev, acc1);
    }
    float dinv = g_deginv[warp];
    g_hN[(size_t)warp * F + lane]      = acc0 * dinv;
    g_hN[(size_t)warp * F + lane + 32] = acc1 * dinv;
}

// ---------------- fused concat-GEMM: out = relu?([h | hN] @ W + b) ----------------
// A0 (per-node features, 64 wide), A1 = g_hN (64 wide), W is [128, NOUT] row-major.
// BM=64 nodes per block; K processed in two halves of 64 to keep smem < 48KB.
template <int NOUT, bool A0_SYM, bool OUT_SYM>
__global__ void k_gemm_concat(const float* __restrict__ A0ext,
                              const float* __restrict__ W,
                              const float* __restrict__ bias,
                              float* __restrict__ outext,
                              int relu) {
    constexpr int BM = 64;
    constexpr int JG = NOUT / 4;      // output thread-groups
    constexpr int NT = 16 * JG;       // threads per block
    constexpr int AP = 66;            // sA pitch (bank-conflict-free scalar reads)

    __shared__ float sA[BM * AP];     // [m][k] for current K-half
    __shared__ float sW[64 * NOUT];   // W rows for current K-half

    const float* __restrict__ A0 = A0_SYM ? (const float*)g_h1 : A0ext;
    const float* __restrict__ A1 = (const float*)g_hN;
    float* __restrict__ out = OUT_SYM ? (float*)g_h1 : outext;

    int tid = threadIdx.x;
    int m0  = blockIdx.x * BM;
    int jg  = tid % JG;   // output group (4 outputs)
    int ng  = tid / JG;   // node group  (4 nodes)

    float acc[4][4];
    float4 b4 = *(const float4*)(bias + jg * 4);
#pragma unroll
    for (int i = 0; i < 4; i++) { acc[i][0] = b4.x; acc[i][1] = b4.y; acc[i][2] = b4.z; acc[i][3] = b4.w; }

#pragma unroll
    for (int half = 0; half < 2; ++half) {
        const float* __restrict__ Asrc = half ? A1 : A0;
        // load A half: 64 nodes x 64 feats (coalesced global reads)
        for (int idx = tid; idx < BM * 64; idx += NT) {
            int m = idx >> 6, k = idx & 63;
            int gm = m0 + m;
            float v = 0.f;
            if (gm < N_NODES) v = Asrc[(size_t)gm * F + k];
            sA[m * AP + k] = v;
        }
        // load W half: rows [half*64, half*64+64)
        for (int idx = tid; idx < 64 * NOUT; idx += NT) {
            sW[idx] = W[half * 64 * NOUT + idx];
        }
        __syncthreads();

        const float* a_base = sA + (ng * 4) * AP;
#pragma unroll 8
        for (int k = 0; k < 64; ++k) {
            float4 w = *(const float4*)(sW + k * NOUT + jg * 4);
            float a0 = a_base[k];
            float a1 = a_base[AP + k];
            float a2 = a_base[2 * AP + k];
            float a3 = a_base[3 * AP + k];
            acc[0][0] = fmaf(a0, w.x, acc[0][0]); acc[0][1] = fmaf(a0, w.y, acc[0][1]);
            acc[0][2] = fmaf(a0, w.z, acc[0][2]); acc[0][3] = fmaf(a0, w.w, acc[0][3]);
            acc[1][0] = fmaf(a1, w.x, acc[1][0]); acc[1][1] = fmaf(a1, w.y, acc[1][1]);
            acc[1][2] = fmaf(a1, w.z, acc[1][2]); acc[1][3] = fmaf(a1, w.w, acc[1][3]);
            acc[2][0] = fmaf(a2, w.x, acc[2][0]); acc[2][1] = fmaf(a2, w.y, acc[2][1]);
            acc[2][2] = fmaf(a2, w.z, acc[2][2]); acc[2][3] = fmaf(a2, w.w, acc[2][3]);
            acc[3][0] = fmaf(a3, w.x, acc[3][0]); acc[3][1] = fmaf(a3, w.y, acc[3][1]);
            acc[3][2] = fmaf(a3, w.z, acc[3][2]); acc[3][3] = fmaf(a3, w.w, acc[3][3]);
        }
        __syncthreads();
    }

#pragma unroll
    for (int i = 0; i < 4; i++) {
        int gm = m0 + ng * 4 + i;
        if (gm < N_NODES) {
            float4 o;
            o.x = acc[i][0]; o.y = acc[i][1]; o.z = acc[i][2]; o.w = acc[i][3];
            if (relu) {
                o.x = fmaxf(o.x, 0.f); o.y = fmaxf(o.y, 0.f);
                o.z = fmaxf(o.z, 0.f); o.w = fmaxf(o.w, 0.f);
            }
            *(float4*)(out + (size_t)gm * NOUT + jg * 4) = o;
        }
    }
}

// ---------------- launch ----------------
extern "C" void kernel_launch(void* const* d_in, const int* in_sizes, int n_in,
                              void* d_out, int out_size) {
    const float* in_feat   = (const float*)d_in[0];
    const float* edge_feat = (const float*)d_in[1];
    const int*   src       = (const int*)d_in[2];
    const int*   dst       = (const int*)d_in[3];
    const float* W1        = (const float*)d_in[4];
    const float* b1        = (const float*)d_in[5];
    const float* W2        = (const float*)d_in[6];
    const float* b2        = (const float*)d_in[7];
    float*       out       = (float*)d_out;

    const int nodeBlocks  = (N_NODES + 255) / 256;
    const int edgeBlocks  = (N_EDGES + 255) / 256;
    const int scanBlocks  = (N_NODES + 1023) / 1024;

    // CSR build (shared by both layers)
    k_zero_deg<<<nodeBlocks, 256>>>();
    k_deg<<<edgeBlocks, 256>>>(dst);
    k_scan_local<<<scanBlocks, 1024>>>();
    k_scan_bsum<<<1, 128>>>(scanBlocks);
    k_scan_add<<<scanBlocks, 1024>>>();
    k_cursor_init<<<nodeBlocks, 256>>>();
    k_fill_csr<<<edgeBlocks, 256>>>(src, dst, edge_feat);

    const int aggBlocks  = (N_NODES * 32 + 255) / 256;
    const int gemmBlocks = (N_NODES + 63) / 64;

    // Layer 1: hN = mean_agg(in_feat); h1 = relu([in_feat | hN] @ W1 + b1)
    k_agg<<<aggBlocks, 256>>>(in_feat, 0);
    k_gemm_concat<64, false, true><<<gemmBlocks, 256>>>(in_feat, W1, b1, nullptr, 1);

    // Layer 2: hN = mean_agg(h1); out = [h1 | hN] @ W2 + b2
    k_agg<<<aggBlocks, 256>>>(nullptr, 1);
    k_gemm_concat<32, true, false><<<gemmBlocks, 128>>>(nullptr, W2, b2, out, 0);
}

// round 3
// speedup vs baseline: 1.0678x; 1.0678x over previous
#include <cuda_runtime.h>
#include <cstdint>

#define N_NODES 100000
#define N_EDGES 1600000
#define F 64

// ---------------- static device scratch ----------------
__device__ int   g_deg[N_NODES];
__device__ int   g_off[N_NODES + 1];
__device__ int   g_cursor[N_NODES];
__device__ int   g_bsum[128];
__device__ int2  g_csr[N_EDGES];              // packed {src, float_bits(e)}
__device__ float g_deginv[N_NODES];
__device__ float g_hN[(size_t)N_NODES * F];   // hN (layer1) / tp (layer2, reused)
__device__ float g_h1[(size_t)N_NODES * F];   // layer-1 output

// ---------------- CSR build ----------------
__global__ void k_zero_deg() {
    int i = blockIdx.x * blockDim.x + threadIdx.x;
    if (i < N_NODES) g_deg[i] = 0;
}

__global__ void k_deg(const int* __restrict__ dst) {
    int i = blockIdx.x * blockDim.x + threadIdx.x;
    if (i < N_EDGES) atomicAdd(&g_deg[dst[i]], 1);
}

__global__ void k_scan_local() {
    __shared__ int sh[1024];
    int i = blockIdx.x * 1024 + threadIdx.x;
    int v = (i < N_NODES) ? g_deg[i] : 0;
    sh[threadIdx.x] = v;
    __syncthreads();
#pragma unroll
    for (int off = 1; off < 1024; off <<= 1) {
        int t = 0;
        if ((int)threadIdx.x >= off) t = sh[threadIdx.x - off];
        __syncthreads();
        sh[threadIdx.x] += t;
        __syncthreads();
    }
    if (i < N_NODES) g_off[i + 1] = sh[threadIdx.x];
    if (threadIdx.x == 1023) g_bsum[blockIdx.x] = sh[1023];
}

__global__ void k_scan_bsum(int nb) {
    __shared__ int sh[128];
    int t = threadIdx.x;
    int v = (t < nb) ? g_bsum[t] : 0;
    sh[t] = v;
    __syncthreads();
#pragma unroll
    for (int off = 1; off < 128; off <<= 1) {
        int x = 0;
        if (t >= off) x = sh[t - off];
        __syncthreads();
        sh[t] += x;
        __syncthreads();
    }
    if (t < nb) g_bsum[t] = sh[t];
}

// merged: finalize scan + init cursor/deginv
__global__ void k_scan_add_cursor() {
    int i = blockIdx.x * blockDim.x + threadIdx.x;
    if (i < N_NODES) {
        int b = i >> 10;
        int val = g_off[i + 1];
        if (b > 0) val += g_bsum[b - 1];
        g_off[i + 1] = val;
        int d = g_deg[i];
        g_cursor[i] = val - d;                 // == final g_off[i]
        g_deginv[i] = 1.0f / (float)(d > 0 ? d : 1);
    }
    if (i == 0) g_off[0] = 0;
}

__global__ void k_fill_csr(const int* __restrict__ src, const int* __restrict__ dst,
                           const float* __restrict__ e) {
    int i = blockIdx.x * blockDim.x + threadIdx.x;
    if (i < N_EDGES) {
        int d = dst[i];
        int pos = atomicAdd(&g_cursor[d], 1);
        g_csr[pos] = make_int2(src[i], __float_as_int(e[i]));
    }
}

// ---------------- aggregation layer 1: 64 feats, 2 edges per warp-step ----------------
__global__ void __launch_bounds__(256) k_agg64(const float* __restrict__ h) {
    int warp = (blockIdx.x * blockDim.x + threadIdx.x) >> 5;
    if (warp >= N_NODES) return;
    int lane = threadIdx.x & 31;
    int g = lane >> 4;      // edge sub-group 0..1
    int c = lane & 15;      // float4 slot

    int beg = g_off[warp], end = g_off[warp + 1];
    float4 acc = make_float4(0.f, 0.f, 0.f, 0.f);
    for (int p = beg; p < end; p += 2) {
        int pe = p + g;
        if (pe < end) {
            int2 se = g_csr[pe];
            float ev = __int_as_float(se.y);
            float4 r = *(const float4*)(h + (size_t)se.x * F + c * 4);
            acc.x = fmaf(r.x, ev, acc.x);
            acc.y = fmaf(r.y, ev, acc.y);
            acc.z = fmaf(r.z, ev, acc.z);
            acc.w = fmaf(r.w, ev, acc.w);
        }
    }
    acc.x += __shfl_xor_sync(0xffffffff, acc.x, 16);
    acc.y += __shfl_xor_sync(0xffffffff, acc.y, 16);
    acc.z += __shfl_xor_sync(0xffffffff, acc.z, 16);
    acc.w += __shfl_xor_sync(0xffffffff, acc.w, 16);
    if (g == 0) {
        float dinv = g_deginv[warp];
        float4 o = make_float4(acc.x * dinv, acc.y * dinv, acc.z * dinv, acc.w * dinv);
        *(float4*)(g_hN + (size_t)warp * F + c * 4) = o;
    }
}

// ---------------- layer-2 aggregation + epilogue: 32 feats, 4 edges per step ----------------
// tp (= g_hN, read via device symbol): tp[n][0..31] = h1@W2_top + b2, tp[n][32..63] = h1@W2_bot
// out[n][j] = tp[n][j] + dinv * sum_e tp[src][32+j]*e
__global__ void __launch_bounds__(256) k_agg32_out(float* __restrict__ out) {
    int warp = (blockIdx.x * blockDim.x + threadIdx.x) >> 5;
    if (warp >= N_NODES) return;
    int lane = threadIdx.x & 31;
    int g = lane >> 3;      // edge sub-group 0..3
    int c = lane & 7;       // float4 slot (8 x float4 = 32 floats)

    const float* __restrict__ tp = (const float*)g_hN;   // device-side symbol ref (valid)

    int beg = g_off[warp], end = g_off[warp + 1];
    float4 acc = make_float4(0.f, 0.f, 0.f, 0.f);
    for (int p = beg; p < end; p += 4) {
        int pe = p + g;
        if (pe < end) {
            int2 se = g_csr[pe];
            float ev = __int_as_float(se.y);
            float4 r = *(const float4*)(tp + (size_t)se.x * 64 + 32 + c * 4);
            acc.x = fmaf(r.x, ev, acc.x);
            acc.y = fmaf(r.y, ev, acc.y);
            acc.z = fmaf(r.z, ev, acc.z);
            acc.w = fmaf(r.w, ev, acc.w);
        }
    }
    acc.x += __shfl_xor_sync(0xffffffff, acc.x, 8);
    acc.y += __shfl_xor_sync(0xffffffff, acc.y, 8);
    acc.z += __shfl_xor_sync(0xffffffff, acc.z, 8);
    acc.w += __shfl_xor_sync(0xffffffff, acc.w, 8);
    acc.x += __shfl_xor_sync(0xffffffff, acc.x, 16);
    acc.y += __shfl_xor_sync(0xffffffff, acc.y, 16);
    acc.z += __shfl_xor_sync(0xffffffff, acc.z, 16);
    acc.w += __shfl_xor_sync(0xffffffff, acc.w, 16);
    if (g == 0) {
        float dinv = g_deginv[warp];
        float4 t = *(const float4*)(tp + (size_t)warp * 64 + c * 4);
        float4 o = make_float4(t.x + acc.x * dinv, t.y + acc.y * dinv,
                               t.z + acc.z * dinv, t.w + acc.w * dinv);
        *(float4*)(out + (size_t)warp * 32 + c * 4) = o;
    }
}

// ---------------- layer-1 GEMM: h1 = relu([in | hN] @ W1 + b1) ----------------
__global__ void __launch_bounds__(256) k_gemm1(const float* __restrict__ A0,
                                               const float* __restrict__ W,
                                               const float* __restrict__ bias) {
    constexpr int NOUT = 64;
    constexpr int BM = 64;
    constexpr int JG = NOUT / 4;   // 16
    constexpr int NT = 256;
    constexpr int AP = 66;

    __shared__ float sA[BM * AP];
    __shared__ float sW[64 * NOUT];

    int tid = threadIdx.x;
    int m0  = blockIdx.x * BM;
    int jg  = tid % JG;
    int ng  = tid / JG;

    float acc[4][4];
    float4 b4 = *(const float4*)(bias + jg * 4);
#pragma unroll
    for (int i = 0; i < 4; i++) { acc[i][0] = b4.x; acc[i][1] = b4.y; acc[i][2] = b4.z; acc[i][3] = b4.w; }

#pragma unroll
    for (int half = 0; half < 2; ++half) {
        const float* __restrict__ Asrc = half ? (const float*)g_hN : A0;
        for (int idx = tid; idx < BM * 64; idx += NT) {
            int m = idx >> 6, k = idx & 63;
            int gm = m0 + m;
            sA[m * AP + k] = (gm < N_NODES) ? Asrc[(size_t)gm * F + k] : 0.f;
        }
        for (int idx = tid; idx < 64 * NOUT; idx += NT)
            sW[idx] = W[half * 64 * NOUT + idx];
        __syncthreads();

        const float* a_base = sA + (ng * 4) * AP;
#pragma unroll 8
        for (int k = 0; k < 64; ++k) {
            float4 w = *(const float4*)(sW + k * NOUT + jg * 4);
            float a0 = a_base[k], a1 = a_base[AP + k], a2 = a_base[2 * AP + k], a3 = a_base[3 * AP + k];
            acc[0][0] = fmaf(a0, w.x, acc[0][0]); acc[0][1] = fmaf(a0, w.y, acc[0][1]);
            acc[0][2] = fmaf(a0, w.z, acc[0][2]); acc[0][3] = fmaf(a0, w.w, acc[0][3]);
            acc[1][0] = fmaf(a1, w.x, acc[1][0]); acc[1][1] = fmaf(a1, w.y, acc[1][1]);
            acc[1][2] = fmaf(a1, w.z, acc[1][2]); acc[1][3] = fmaf(a1, w.w, acc[1][3]);
            acc[2][0] = fmaf(a2, w.x, acc[2][0]); acc[2][1] = fmaf(a2, w.y, acc[2][1]);
            acc[2][2] = fmaf(a2, w.z, acc[2][2]); acc[2][3] = fmaf(a2, w.w, acc[2][3]);
            acc[3][0] = fmaf(a3, w.x, acc[3][0]); acc[3][1] = fmaf(a3, w.y, acc[3][1]);
            acc[3][2] = fmaf(a3, w.z, acc[3][2]); acc[3][3] = fmaf(a3, w.w, acc[3][3]);
        }
        __syncthreads();
    }

#pragma unroll
    for (int i = 0; i < 4; i++) {
        int gm = m0 + ng * 4 + i;
        if (gm < N_NODES) {
            float4 o = make_float4(fmaxf(acc[i][0], 0.f), fmaxf(acc[i][1], 0.f),
                                   fmaxf(acc[i][2], 0.f), fmaxf(acc[i][3], 0.f));
            *(float4*)(g_h1 + (size_t)gm * NOUT + jg * 4) = o;
        }
    }
}

// ---------------- layer-2 GEMM (combined): tp = [h1@W2_top + b2 | h1@W2_bot] ----------------
// W2 is [128,32] row-major; K=64 (h1 width). tp written to g_hN.
__global__ void __launch_bounds__(256) k_gemm2(const float* __restrict__ W2,
                                               const float* __restrict__ b2) {
    constexpr int NOUT = 64;   // 32 top | 32 bottom
    constexpr int BM = 64;
    constexpr int JG = NOUT / 4;   // 16
    constexpr int NT = 256;
    constexpr int AP = 66;

    __shared__ float sA[BM * AP];
    __shared__ float sW[64 * NOUT];

    int tid = threadIdx.x;
    int m0  = blockIdx.x * BM;
    int jg  = tid % JG;
    int ng  = tid / JG;

    float acc[4][4];
    if (jg < 8) {   // outputs 0..31 get bias
        float4 b4 = *(const float4*)(b2 + jg * 4);
#pragma unroll
        for (int i = 0; i < 4; i++) { acc[i][0] = b4.x; acc[i][1] = b4.y; acc[i][2] = b4.z; acc[i][3] = b4.w; }
    } else {
#pragma unroll
        for (int i = 0; i < 4; i++) { acc[i][0] = 0.f; acc[i][1] = 0.f; acc[i][2] = 0.f; acc[i][3] = 0.f; }
    }

    // load A: 64 nodes x 64 feats of h1
    for (int idx = tid; idx < BM * 64; idx += NT) {
        int m = idx >> 6, k = idx & 63;
        int gm = m0 + m;
        sA[m * AP + k] = (gm < N_NODES) ? g_h1[(size_t)gm * F + k] : 0.f;
    }
    // load combined W: sW[k][j] = j<32 ? W2[k][j] : W2[64+k][j-32]
    for (int idx = tid; idx < 64 * NOUT; idx += NT) {
        int k = idx >> 6, j = idx & 63;
        sW[idx] = (j < 32) ? W2[k * 32 + j] : W2[(64 + k) * 32 + (j - 32)];
    }
    __syncthreads();

    const float* a_base = sA + (ng * 4) * AP;
#pragma unroll 8
    for (int k = 0; k < 64; ++k) {
        float4 w = *(const float4*)(sW + k * NOUT + jg * 4);
        float a0 = a_base[k], a1 = a_base[AP + k], a2 = a_base[2 * AP + k], a3 = a_base[3 * AP + k];
        acc[0][0] = fmaf(a0, w.x, acc[0][0]); acc[0][1] = fmaf(a0, w.y, acc[0][1]);
        acc[0][2] = fmaf(a0, w.z, acc[0][2]); acc[0][3] = fmaf(a0, w.w, acc[0][3]);
        acc[1][0] = fmaf(a1, w.x, acc[1][0]); acc[1][1] = fmaf(a1, w.y, acc[1][1]);
        acc[1][2] = fmaf(a1, w.z, acc[1][2]); acc[1][3] = fmaf(a1, w.w, acc[1][3]);
        acc[2][0] = fmaf(a2, w.x, acc[2][0]); acc[2][1] = fmaf(a2, w.y, acc[2][1]);
        acc[2][2] = fmaf(a2, w.z, acc[2][2]); acc[2][3] = fmaf(a2, w.w, acc[2][3]);
        acc[3][0] = fmaf(a3, w.x, acc[3][0]); acc[3][1] = fmaf(a3, w.y, acc[3][1]);
        acc[3][2] = fmaf(a3, w.z, acc[3][2]); acc[3][3] = fmaf(a3, w.w, acc[3][3]);
    }

#pragma unroll
    for (int i = 0; i < 4; i++) {
        int gm = m0 + ng * 4 + i;
        if (gm < N_NODES) {
            float4 o = make_float4(acc[i][0], acc[i][1], acc[i][2], acc[i][3]);
            *(float4*)(g_hN + (size_t)gm * NOUT + jg * 4) = o;   // tp stored in g_hN
        }
    }
}

// ---------------- launch ----------------
extern "C" void kernel_launch(void* const* d_in, const int* in_sizes, int n_in,
                              void* d_out, int out_size) {
    const float* in_feat   = (const float*)d_in[0];
    const float* edge_feat = (const float*)d_in[1];
    const int*   src       = (const int*)d_in[2];
    const int*   dst       = (const int*)d_in[3];
    const float* W1        = (const float*)d_in[4];
    const float* b1        = (const float*)d_in[5];
    const float* W2        = (const float*)d_in[6];
    const float* b2        = (const float*)d_in[7];
    float*       out       = (float*)d_out;

    const int nodeBlocks = (N_NODES + 255) / 256;
    const int edgeBlocks = (N_EDGES + 255) / 256;
    const int scanBlocks = (N_NODES + 1023) / 1024;
    const int aggBlocks  = (N_NODES * 32 + 255) / 256;
    const int gemmBlocks = (N_NODES + 63) / 64;

    // CSR build (shared by both layers)
    k_zero_deg<<<nodeBlocks, 256>>>();
    k_deg<<<edgeBlocks, 256>>>(dst);
    k_scan_local<<<scanBlocks, 1024>>>();
    k_scan_bsum<<<1, 128>>>(scanBlocks);
    k_scan_add_cursor<<<scanBlocks, 1024>>>();
    k_fill_csr<<<edgeBlocks, 256>>>(src, dst, edge_feat);

    // Layer 1: hN = Agg(in); h1 = relu([in | hN] @ W1 + b1)
    k_agg64<<<aggBlocks, 256>>>(in_feat);
    k_gemm1<<<gemmBlocks, 256>>>(in_feat, W1, b1);

    // Layer 2 (project-then-aggregate): tp = [h1@W2_top+b2 | h1@W2_bot]
    // out = tp_top + Agg(tp_bot)
    k_gemm2<<<gemmBlocks, 256>>>(W2, b2);
    k_agg32_out<<<aggBlocks, 256>>>(out);
}

// round 4
// speedup vs baseline: 1.1491x; 1.0761x over previous
#include <cuda_runtime.h>
#include <cstdint>

#define N_NODES 100000
#define N_EDGES 1600000
#define F 64

// ---------------- static device scratch ----------------
__device__ int   g_deg[N_NODES];
__device__ int   g_off[N_NODES + 1];
__device__ int   g_cursor[N_NODES];
__device__ int   g_bsum[128];
__device__ int2  g_csr[N_EDGES];              // packed {src, float_bits(e)}
__device__ float g_deginv[N_NODES];
__device__ float g_hN[(size_t)N_NODES * F];   // hN (layer1) / tp (layer2, reused)
__device__ float g_h1[(size_t)N_NODES * F];   // layer-1 output

// ---------------- f32x2 packed-FMA helpers (Blackwell FFMA2) ----------------
__device__ __forceinline__ unsigned long long pack2(float a) {
    unsigned long long r;
    asm("mov.b64 %0, {%1, %1};" : "=l"(r) : "f"(a));
    return r;
}
__device__ __forceinline__ void ffma2(unsigned long long& d,
                                      unsigned long long a, unsigned long long b) {
    asm("fma.rn.f32x2 %0, %1, %2, %0;" : "+l"(d) : "l"(a), "l"(b));
}
__device__ __forceinline__ float2 unpack2(unsigned long long v) {
    float lo, hi;
    asm("mov.b64 {%0, %1}, %2;" : "=f"(lo), "=f"(hi) : "l"(v));
    return make_float2(lo, hi);
}

// ---------------- CSR build ----------------
__global__ void k_deg(const int4* __restrict__ dst4) {
    int i = blockIdx.x * blockDim.x + threadIdx.x;
    if (i < N_EDGES / 4) {
        int4 d = dst4[i];
        atomicAdd(&g_deg[d.x], 1);
        atomicAdd(&g_deg[d.y], 1);
        atomicAdd(&g_deg[d.z], 1);
        atomicAdd(&g_deg[d.w], 1);
    }
}

__global__ void k_scan_local() {
    __shared__ int sh[1024];
    int i = blockIdx.x * 1024 + threadIdx.x;
    int v = (i < N_NODES) ? g_deg[i] : 0;
    sh[threadIdx.x] = v;
    __syncthreads();
#pragma unroll
    for (int off = 1; off < 1024; off <<= 1) {
        int t = 0;
        if ((int)threadIdx.x >= off) t = sh[threadIdx.x - off];
        __syncthreads();
        sh[threadIdx.x] += t;
        __syncthreads();
    }
    if (i < N_NODES) g_off[i + 1] = sh[threadIdx.x];
    if (threadIdx.x == 1023) g_bsum[blockIdx.x] = sh[1023];
}

__global__ void k_scan_bsum(int nb) {
    __shared__ int sh[128];
    int t = threadIdx.x;
    int v = (t < nb) ? g_bsum[t] : 0;
    sh[t] = v;
    __syncthreads();
#pragma unroll
    for (int off = 1; off < 128; off <<= 1) {
        int x = 0;
        if (t >= off) x = sh[t - off];
        __syncthreads();
        sh[t] += x;
        __syncthreads();
    }
    if (t < nb) g_bsum[t] = sh[t];
}

__global__ void k_scan_add_cursor() {
    int i = blockIdx.x * blockDim.x + threadIdx.x;
    if (i < N_NODES) {
        int b = i >> 10;
        int val = g_off[i + 1];
        if (b > 0) val += g_bsum[b - 1];
        g_off[i + 1] = val;
        int d = g_deg[i];
        g_cursor[i] = val - d;                 // == final g_off[i]
        g_deginv[i] = 1.0f / (float)(d > 0 ? d : 1);
    }
    if (i == 0) g_off[0] = 0;
}

__global__ void k_fill_csr(const int4* __restrict__ src4, const int4* __restrict__ dst4,
                           const float4* __restrict__ e4) {
    int i = blockIdx.x * blockDim.x + threadIdx.x;
    if (i < N_EDGES / 4) {
        int4 s = src4[i];
        int4 d = dst4[i];
        float4 e = e4[i];
        int p0 = atomicAdd(&g_cursor[d.x], 1);
        g_csr[p0] = make_int2(s.x, __float_as_int(e.x));
        int p1 = atomicAdd(&g_cursor[d.y], 1);
        g_csr[p1] = make_int2(s.y, __float_as_int(e.y));
        int p2 = atomicAdd(&g_cursor[d.z], 1);
        g_csr[p2] = make_int2(s.z, __float_as_int(e.z));
        int p3 = atomicAdd(&g_cursor[d.w], 1);
        g_csr[p3] = make_int2(s.w, __float_as_int(e.w));
    }
}

// ---------------- aggregation layer 1: 64 feats, 2 edges per warp-step ----------------
__global__ void __launch_bounds__(256) k_agg64(const float* __restrict__ h) {
    int warp = (blockIdx.x * blockDim.x + threadIdx.x) >> 5;
    if (warp >= N_NODES) return;
    int lane = threadIdx.x & 31;
    int g = lane >> 4;      // edge sub-group 0..1
    int c = lane & 15;      // float4 slot

    int beg = g_off[warp], end = g_off[warp + 1];
    float4 acc = make_float4(0.f, 0.f, 0.f, 0.f);
#pragma unroll 4
    for (int p = beg; p < end; p += 2) {
        int pe = p + g;
        if (pe < end) {
            int2 se = g_csr[pe];
            float ev = __int_as_float(se.y);
            float4 r = *(const float4*)(h + (size_t)se.x * F + c * 4);
            acc.x = fmaf(r.x, ev, acc.x);
            acc.y = fmaf(r.y, ev, acc.y);
            acc.z = fmaf(r.z, ev, acc.z);
            acc.w = fmaf(r.w, ev, acc.w);
        }
    }
    acc.x += __shfl_xor_sync(0xffffffff, acc.x, 16);
    acc.y += __shfl_xor_sync(0xffffffff, acc.y, 16);
    acc.z += __shfl_xor_sync(0xffffffff, acc.z, 16);
    acc.w += __shfl_xor_sync(0xffffffff, acc.w, 16);
    if (g == 0) {
        float dinv = g_deginv[warp];
        float4 o = make_float4(acc.x * dinv, acc.y * dinv, acc.z * dinv, acc.w * dinv);
        *(float4*)(g_hN + (size_t)warp * F + c * 4) = o;
    }
}

// ---------------- layer-2 aggregation + epilogue: 32 feats, 4 edges per step ----------------
// tp (= g_hN): tp[n][0..31] = h1@W2_top + b2, tp[n][32..63] = h1@W2_bot
// out[n][j] = tp[n][j] + dinv * sum_e tp[src][32+j]*e
__global__ void __launch_bounds__(256) k_agg32_out(float* __restrict__ out) {
    int warp = (blockIdx.x * blockDim.x + threadIdx.x) >> 5;
    if (warp >= N_NODES) return;
    int lane = threadIdx.x & 31;
    int g = lane >> 3;      // edge sub-group 0..3
    int c = lane & 7;       // float4 slot

    const float* __restrict__ tp = (const float*)g_hN;

    int beg = g_off[warp], end = g_off[warp + 1];
    float4 acc = make_float4(0.f, 0.f, 0.f, 0.f);
#pragma unroll 4
    for (int p = beg; p < end; p += 4) {
        int pe = p + g;
        if (pe < end) {
            int2 se = g_csr[pe];
            float ev = __int_as_float(se.y);
            float4 r = *(const float4*)(tp + (size_t)se.x * 64 + 32 + c * 4);
            acc.x = fmaf(r.x, ev, acc.x);
            acc.y = fmaf(r.y, ev, acc.y);
            acc.z = fmaf(r.z, ev, acc.z);
            acc.w = fmaf(r.w, ev, acc.w);
        }
    }
    acc.x += __shfl_xor_sync(0xffffffff, acc.x, 8);
    acc.y += __shfl_xor_sync(0xffffffff, acc.y, 8);
    acc.z += __shfl_xor_sync(0xffffffff, acc.z, 8);
    acc.w += __shfl_xor_sync(0xffffffff, acc.w, 8);
    acc.x += __shfl_xor_sync(0xffffffff, acc.x, 16);
    acc.y += __shfl_xor_sync(0xffffffff, acc.y, 16);
    acc.z += __shfl_xor_sync(0xffffffff, acc.z, 16);
    acc.w += __shfl_xor_sync(0xffffffff, acc.w, 16);
    if (g == 0) {
        float dinv = g_deginv[warp];
        float4 t = *(const float4*)(tp + (size_t)warp * 64 + c * 4);
        float4 o = make_float4(t.x + acc.x * dinv, t.y + acc.y * dinv,
                               t.z + acc.z * dinv, t.w + acc.w * dinv);
        *(float4*)(out + (size_t)warp * 32 + c * 4) = o;
    }
}

// ---------------- layer-1 GEMM (f32x2): h1 = relu([in | hN] @ W1 + b1) ----------------
__global__ void __launch_bounds__(256) k_gemm1(const float* __restrict__ A0,
                                               const float* __restrict__ W,
                                               const float* __restrict__ bias) {
    constexpr int NOUT = 64;
    constexpr int BM = 64;
    constexpr int JG = NOUT / 4;   // 16 (4 outputs = 2 packed pairs per thread)
    constexpr int NT = 256;
    constexpr int AP = 68;         // pitch: 16B-aligned float4 stores, conflict-free reads

    __shared__ __align__(16) float sA[BM * AP];
    __shared__ __align__(16) float sW[64 * NOUT];

    int tid = threadIdx.x;
    int m0  = blockIdx.x * BM;
    int jg  = tid % JG;
    int ng  = tid / JG;

    unsigned long long acc[4][2];
    {
        ulonglong2 b2v = *(const ulonglong2*)(bias + jg * 4);
#pragma unroll
        for (int i = 0; i < 4; i++) { acc[i][0] = b2v.x; acc[i][1] = b2v.y; }
    }

#pragma unroll
    for (int half = 0; half < 2; ++half) {
        const float* __restrict__ Asrc = half ? (const float*)g_hN : A0;
        for (int idx = tid; idx < BM * 16; idx += NT) {
            int m = idx >> 4, kq = idx & 15;
            int gm = m0 + m;
            float4 v = make_float4(0.f, 0.f, 0.f, 0.f);
            if (gm < N_NODES) v = *(const float4*)(Asrc + (size_t)gm * F + kq * 4);
            *(float4*)(sA + m * AP + kq * 4) = v;
        }
        for (int idx = tid; idx < 64 * NOUT / 4; idx += NT) {
            *(float4*)(sW + idx * 4) = *(const float4*)(W + half * 64 * NOUT + idx * 4);
        }
        __syncthreads();

        const float* a_base = sA + (ng * 4) * AP;
#pragma unroll 8
        for (int k = 0; k < 64; ++k) {
            ulonglong2 w2 = *(const ulonglong2*)(sW + k * NOUT + jg * 4);
            unsigned long long a0 = pack2(a_base[k]);
            unsigned long long a1 = pack2(a_base[AP + k]);
            unsigned long long a2 = pack2(a_base[2 * AP + k]);
            unsigned long long a3 = pack2(a_base[3 * AP + k]);
            ffma2(acc[0][0], a0, w2.x); ffma2(acc[0][1], a0, w2.y);
            ffma2(acc[1][0], a1, w2.x); ffma2(acc[1][1], a1, w2.y);
            ffma2(acc[2][0], a2, w2.x); ffma2(acc[2][1], a2, w2.y);
            ffma2(acc[3][0], a3, w2.x); ffma2(acc[3][1], a3, w2.y);
        }
        __syncthreads();
    }

#pragma unroll
    for (int i = 0; i < 4; i++) {
        int gm = m0 + ng * 4 + i;
        if (gm < N_NODES) {
            float2 lo = unpack2(acc[i][0]);
            float2 hi = unpack2(acc[i][1]);
            float4 o = make_float4(fmaxf(lo.x, 0.f), fmaxf(lo.y, 0.f),
                                   fmaxf(hi.x, 0.f), fmaxf(hi.y, 0.f));
            *(float4*)(g_h1 + (size_t)gm * NOUT + jg * 4) = o;
        }
    }
}

// ---------------- layer-2 GEMM (f32x2, combined): tp = [h1@W2_top + b2 | h1@W2_bot] ----------------
__global__ void __launch_bounds__(256) k_gemm2(const float* __restrict__ W2,
                                               const float* __restrict__ b2) {
    constexpr int NOUT = 64;   // 32 top | 32 bottom
    constexpr int BM = 64;
    constexpr int JG = NOUT / 4;   // 16
    constexpr int NT = 256;
    constexpr int AP = 68;

    __shared__ __align__(16) float sA[BM * AP];
    __shared__ __align__(16) float sW[64 * NOUT];

    int tid = threadIdx.x;
    int m0  = blockIdx.x * BM;
    int jg  = tid % JG;
    int ng  = tid / JG;

    unsigned long long acc[4][2];
    if (jg < 8) {
        ulonglong2 b2v = *(const ulonglong2*)(b2 + jg * 4);
#pragma unroll
        for (int i = 0; i < 4; i++) { acc[i][0] = b2v.x; acc[i][1] = b2v.y; }
    } else {
#pragma unroll
        for (int i = 0; i < 4; i++) { acc[i][0] = 0ull; acc[i][1] = 0ull; }
    }

    for (int idx = tid; idx < BM * 16; idx += NT) {
        int m = idx >> 4, kq = idx & 15;
        int gm = m0 + m;
        float4 v = make_float4(0.f, 0.f, 0.f, 0.f);
        if (gm < N_NODES) v = *(const float4*)(g_h1 + (size_t)gm * F + kq * 4);
        *(float4*)(sA + m * AP + kq * 4) = v;
    }
    // combined W: sW[k][j] = j<32 ? W2[k][j] : W2[64+k][j-32]   (float4 granular)
    for (int idx = tid; idx < 64 * NOUT / 4; idx += NT) {
        int k = idx >> 4, jq = idx & 15;
        float4 v;
        if (jq < 8) v = *(const float4*)(W2 + k * 32 + jq * 4);
        else        v = *(const float4*)(W2 + (64 + k) * 32 + (jq - 8) * 4);
        *(float4*)(sW + k * NOUT + jq * 4) = v;
    }
    __syncthreads();

    const float* a_base = sA + (ng * 4) * AP;
#pragma unroll 8
    for (int k = 0; k < 64; ++k) {
        ulonglong2 w2 = *(const ulonglong2*)(sW + k * NOUT + jg * 4);
        unsigned long long a0 = pack2(a_base[k]);
        unsigned long long a1 = pack2(a_base[AP + k]);
        unsigned long long a2 = pack2(a_base[2 * AP + k]);
        unsigned long long a3 = pack2(a_base[3 * AP + k]);
        ffma2(acc[0][0], a0, w2.x); ffma2(acc[0][1], a0, w2.y);
        ffma2(acc[1][0], a1, w2.x); ffma2(acc[1][1], a1, w2.y);
        ffma2(acc[2][0], a2, w2.x); ffma2(acc[2][1], a2, w2.y);
        ffma2(acc[3][0], a3, w2.x); ffma2(acc[3][1], a3, w2.y);
    }

#pragma unroll
    for (int i = 0; i < 4; i++) {
        int gm = m0 + ng * 4 + i;
        if (gm < N_NODES) {
            float2 lo = unpack2(acc[i][0]);
            float2 hi = unpack2(acc[i][1]);
            float4 o = make_float4(lo.x, lo.y, hi.x, hi.y);
            *(float4*)(g_hN + (size_t)gm * NOUT + jg * 4) = o;   // tp stored in g_hN
        }
    }
}

// ---------------- launch ----------------
extern "C" void kernel_launch(void* const* d_in, const int* in_sizes, int n_in,
                              void* d_out, int out_size) {
    const float* in_feat   = (const float*)d_in[0];
    const float* edge_feat = (const float*)d_in[1];
    const int*   src       = (const int*)d_in[2];
    const int*   dst       = (const int*)d_in[3];
    const float* W1        = (const float*)d_in[4];
    const float* b1        = (const float*)d_in[5];
    const float* W2        = (const float*)d_in[6];
    const float* b2        = (const float*)d_in[7];
    float*       out       = (float*)d_out;

    const int nodeBlocks  = (N_NODES + 255) / 256;
    const int edge4Blocks = (N_EDGES / 4 + 255) / 256;
    const int scanBlocks  = (N_NODES + 1023) / 1024;
    const int aggBlocks   = (N_NODES * 32 + 255) / 256;
    const int gemmBlocks  = (N_NODES + 63) / 64;

    // zero degree via memset node (no kernel launch)
    void* degPtr = nullptr;
    cudaGetSymbolAddress(&degPtr, g_deg);
    cudaMemsetAsync(degPtr, 0, N_NODES * sizeof(int));

    // CSR build (shared by both layers)
    k_deg<<<edge4Blocks, 256>>>((const int4*)dst);
    k_scan_local<<<scanBlocks, 1024>>>();
    k_scan_bsum<<<1, 128>>>(scanBlocks);
    k_scan_add_cursor<<<nodeBlocks, 256>>>();
    k_fill_csr<<<edge4Blocks, 256>>>((const int4*)src, (const int4*)dst,
                                     (const float4*)edge_feat);

    // Layer 1: hN = Agg(in); h1 = relu([in | hN] @ W1 + b1)
    k_agg64<<<aggBlocks, 256>>>(in_feat);
    k_gemm1<<<gemmBlocks, 256>>>(in_feat, W1, b1);

    // Layer 2 (project-then-aggregate): tp = [h1@W2_top+b2 | h1@W2_bot]
    // out = tp_top + Agg(tp_bot)
    k_gemm2<<<gemmBlocks, 256>>>(W2, b2);
    k_agg32_out<<<aggBlocks, 256>>>(out);
}